// round 2
// baseline (speedup 1.0000x reference)
#include <cuda_runtime.h>

#define N_NODES 50000
#define N_EDGES 600000
#define D 128
#define NLAYERS 5

typedef unsigned long long ull;

// ----------------- persistent device scratch -----------------
__device__ float g_h[N_NODES * D];      // layer-0 input embeddings
__device__ float g_z[N_NODES * D];      // z = h + agg
__device__ float g_out[N_NODES * D];    // MLP output (pre-BN)
__device__ float g_etab[9 * D];         // 9 distinct edge vectors
__device__ float g_stats[2 * D];        // column sum, sumsq
__device__ float g_aff[2 * D];          // per-feature scale, shift (BN folded)
__device__ int   g_deg[N_NODES];
__device__ int   g_off[N_NODES + 1];
__device__ int   g_cur[N_NODES];
__device__ int   g_csr[N_EDGES];        // src | (edge_code << 20)
__device__ int   g_is64;                // 1 if integer inputs are int64

// ----------------- f32x2 helpers (Blackwell packed FMA) -----------------
__device__ __forceinline__ ull splat2(float x) {
    ull r;
    asm("mov.b64 %0, {%1, %1};" : "=l"(r) : "f"(x));
    return r;
}
__device__ __forceinline__ void ffma2(ull& d, ull a, ull b) {
    asm("fma.rn.f32x2 %0, %1, %2, %0;" : "+l"(d) : "l"(a), "l"(b));
}
__device__ __forceinline__ void unpack2(ull v, float& lo, float& hi) {
    asm("mov.b64 {%0, %1}, %2;" : "=f"(lo), "=f"(hi) : "l"(v));
}

// logical integer index -> value, handling int32 or int64 (little-endian lo word)
__device__ __forceinline__ int getidx(const int* __restrict__ p, int i) {
    return g_is64 ? p[2 * i] : p[i];
}

// ----------------- dtype detection -----------------
__global__ void k_detect(const int* __restrict__ x) {
    if (threadIdx.x == 0) {
        int nz = 0;
        for (int i = 1; i < 128; i += 2) nz |= x[i];
        g_is64 = (nz == 0) ? 1 : 0;
    }
}

// ----------------- setup kernels -----------------
__global__ void k_embed(const int* __restrict__ x,
                        const float* __restrict__ elem,
                        const float* __restrict__ chir) {
    int i = blockIdx.x * blockDim.x + threadIdx.x;   // float4 slots
    if (i >= N_NODES * 32) return;
    int node = i >> 5, l = i & 31;
    int a = getidx(x, 2 * node);
    int c = getidx(x, 2 * node + 1);
    float4 va = __ldg((const float4*)(elem + a * D) + l);
    float4 vc = __ldg((const float4*)(chir + c * D) + l);
    float4 o = make_float4(va.x + vc.x, va.y + vc.y, va.z + vc.z, va.w + vc.w);
    ((float4*)(g_h + node * D))[l] = o;
}

__global__ void k_etab(const float* __restrict__ bt, const float* __restrict__ bd) {
    int code = blockIdx.x;          // 0..8
    int t = code / 3, d = code % 3;
    int c = threadIdx.x;
    g_etab[code * D + c] = bt[t * D + c] + bd[d * D + c];
}

__global__ void k_zero_deg() {
    int i = blockIdx.x * blockDim.x + threadIdx.x;
    if (i < N_NODES) g_deg[i] = 0;
}

__global__ void k_hist(const int* __restrict__ ei) {
    int e = blockIdx.x * blockDim.x + threadIdx.x;
    if (e < N_EDGES) {
        int dst = getidx(ei, N_EDGES + e);
        atomicAdd(&g_deg[dst], 1);
    }
}

__global__ void k_scan() {
    __shared__ int sh[1024];
    __shared__ int carry_s;
    int tid = threadIdx.x;
    if (tid == 0) carry_s = 0;
    __syncthreads();
    for (int base = 0; base < N_NODES; base += 1024) {
        int i = base + tid;
        int v = (i < N_NODES) ? g_deg[i] : 0;
        sh[tid] = v;
        __syncthreads();
        for (int off = 1; off < 1024; off <<= 1) {
            int t = (tid >= off) ? sh[tid - off] : 0;
            __syncthreads();
            sh[tid] += t;
            __syncthreads();
        }
        int incl = sh[tid];
        int c = carry_s;
        if (i < N_NODES) {
            g_off[i] = c + incl - v;
            g_cur[i] = c + incl - v;
        }
        __syncthreads();
        if (tid == 1023) carry_s = c + incl;
        __syncthreads();
    }
    if (tid == 0) g_off[N_NODES] = carry_s;
}

__global__ void k_fill(const int* __restrict__ ei, const int* __restrict__ ea) {
    int e = blockIdx.x * blockDim.x + threadIdx.x;
    if (e < N_EDGES) {
        int src = getidx(ei, e);
        int dst = getidx(ei, N_EDGES + e);
        int t = getidx(ea, 2 * e);
        int d = getidx(ea, 2 * e + 1);
        int pos = atomicAdd(&g_cur[dst], 1);
        g_csr[pos] = src | ((t * 3 + d) << 20);
    }
}

__global__ void k_zero_stats() {
    int i = threadIdx.x;
    if (i < 2 * D) g_stats[i] = 0.f;
}

// ----------------- aggregation: one warp per dst node -----------------
// input transform t(): layer 0 -> identity (reads g_h); layers>=1 ->
// relu(v*scale + shift) applied on the fly to prev layer's g_out.
__global__ void __launch_bounds__(256) k_agg(int layer) {
    __shared__ float et[9 * D];
    __shared__ float aff[2 * D];
    int tid = threadIdx.x;
    for (int i = tid; i < 9 * D; i += 256) et[i] = g_etab[i];
    if (tid < 2 * D) aff[tid] = g_aff[tid];
    __syncthreads();

    const int mode = (layer > 0);
    const float* __restrict__ in = mode ? g_out : g_h;

    int warp = tid >> 5, lane = tid & 31;
    int node = blockIdx.x * 8 + warp;
    if (node >= N_NODES) return;
    int c0 = lane * 4;

    float4 sc = make_float4(1.f, 1.f, 1.f, 1.f);
    float4 sf = make_float4(0.f, 0.f, 0.f, 0.f);
    if (mode) {
        sc = *(float4*)&aff[c0];
        sf = *(float4*)&aff[D + c0];
    }

    int beg = g_off[node], end = g_off[node + 1];
    float4 acc = make_float4(0.f, 0.f, 0.f, 0.f);

    for (int e0 = beg; e0 < end; e0 += 32) {
        int v = 0;
        if (e0 + lane < end) v = g_csr[e0 + lane];
        int cnt = min(32, end - e0);
        for (int j = 0; j < cnt; j++) {
            int vv = __shfl_sync(0xffffffffu, v, j);
            int src = vv & 0xFFFFF;
            int code = vv >> 20;
            float4 hv = __ldg((const float4*)(in + src * D) + lane);
            if (mode) {
                hv.x = fmaxf(fmaf(hv.x, sc.x, sf.x), 0.f);
                hv.y = fmaxf(fmaf(hv.y, sc.y, sf.y), 0.f);
                hv.z = fmaxf(fmaf(hv.z, sc.z, sf.z), 0.f);
                hv.w = fmaxf(fmaf(hv.w, sc.w, sf.w), 0.f);
            }
            const float* ep = et + code * D + c0;
            float4 ev = *(const float4*)ep;
            acc.x += fmaxf(hv.x + ev.x, 0.f);
            acc.y += fmaxf(hv.y + ev.y, 0.f);
            acc.z += fmaxf(hv.z + ev.z, 0.f);
            acc.w += fmaxf(hv.w + ev.w, 0.f);
        }
    }
    float4 hd = __ldg((const float4*)(in + node * D) + lane);
    if (mode) {
        hd.x = fmaxf(fmaf(hd.x, sc.x, sf.x), 0.f);
        hd.y = fmaxf(fmaf(hd.y, sc.y, sf.y), 0.f);
        hd.z = fmaxf(fmaf(hd.z, sc.z, sf.z), 0.f);
        hd.w = fmaxf(fmaf(hd.w, sc.w, sf.w), 0.f);
    }
    acc.x += hd.x; acc.y += hd.y; acc.z += hd.z; acc.w += hd.w;
    *(float4*)(g_z + node * D + c0) = acc;
}

// ----------------- fused MLP: out = relu(z@W1+b1)@W2+b2, + BN stats -----------
// 64 rows per block, 256 threads, f32x2 packed FMA, fp32 accuracy.
#define ZS_STRIDE 132
#define HS_STRIDE 260
#define SMEM_MLP (64 * ZS_STRIDE * 4 + 64 * HS_STRIDE * 4)

__global__ void __launch_bounds__(256, 2) k_mlp(const float* __restrict__ W1,
                                                const float* __restrict__ b1,
                                                const float* __restrict__ W2,
                                                const float* __restrict__ b2) {
    extern __shared__ float sm[];
    float* zs = sm;                        // [64][132]
    float* hs = sm + 64 * ZS_STRIDE;       // [64][260]
    const int tid = threadIdx.x;
    const int rowBase = blockIdx.x * 64;

    // stage z tile
    for (int i = tid; i < 64 * 32; i += 256) {
        int r = i >> 5, c4 = i & 31;
        int row = rowBase + r;
        float4 v = make_float4(0.f, 0.f, 0.f, 0.f);
        if (row < N_NODES) v = __ldg((const float4*)(g_z + row * D) + c4);
        *(float4*)(zs + r * ZS_STRIDE + c4 * 4) = v;
    }
    __syncthreads();

    const int cx = tid & 31;    // col group: 8 cols
    const int ry = tid >> 5;    // row group: 8 rows

    // Phase A: hidden[64][256] = relu(z @ W1 + b1)
    {
        ull acc[8][4];
        const float* bp0 = b1 + cx * 8;
#pragma unroll
        for (int p = 0; p < 4; p++) {
            ull bp = ((const ull*)bp0)[p];
#pragma unroll
            for (int r = 0; r < 8; r++) acc[r][p] = bp;
        }
        const float* zrow = zs + ry * 8 * ZS_STRIDE;
        const float* wp = W1 + cx * 8;
        for (int k = 0; k < D; k++) {
            ulonglong2 wa = *(const ulonglong2*)(wp + k * 256);
            ulonglong2 wb = *(const ulonglong2*)(wp + k * 256 + 4);
#pragma unroll
            for (int r = 0; r < 8; r++) {
                ull zz = splat2(zrow[r * ZS_STRIDE + k]);
                ffma2(acc[r][0], zz, wa.x);
                ffma2(acc[r][1], zz, wa.y);
                ffma2(acc[r][2], zz, wb.x);
                ffma2(acc[r][3], zz, wb.y);
            }
        }
#pragma unroll
        for (int r = 0; r < 8; r++) {
            float* hrow = hs + (ry * 8 + r) * HS_STRIDE + cx * 8;
#pragma unroll
            for (int p = 0; p < 4; p++) {
                float lo, hi;
                unpack2(acc[r][p], lo, hi);
                hrow[2 * p]     = fmaxf(lo, 0.f);
                hrow[2 * p + 1] = fmaxf(hi, 0.f);
            }
        }
    }
    __syncthreads();

    // Phase B: out[64][128] = hidden @ W2 + b2
    const int cx2 = tid & 31;   // 4 cols
    const int ry2 = tid >> 5;   // 8 rows
    float ov[8][4];
    {
        ull acc[8][2];
        const float* bp0 = b2 + cx2 * 4;
#pragma unroll
        for (int p = 0; p < 2; p++) {
            ull bp = ((const ull*)bp0)[p];
#pragma unroll
            for (int r = 0; r < 8; r++) acc[r][p] = bp;
        }
        const float* hrow0 = hs + ry2 * 8 * HS_STRIDE;
        const float* wp = W2 + cx2 * 4;
        for (int k = 0; k < 256; k++) {
            ulonglong2 w = *(const ulonglong2*)(wp + k * 128);
#pragma unroll
            for (int r = 0; r < 8; r++) {
                ull zz = splat2(hrow0[r * HS_STRIDE + k]);
                ffma2(acc[r][0], zz, w.x);
                ffma2(acc[r][1], zz, w.y);
            }
        }
#pragma unroll
        for (int r = 0; r < 8; r++) {
            unpack2(acc[r][0], ov[r][0], ov[r][1]);
            unpack2(acc[r][1], ov[r][2], ov[r][3]);
        }
    }

    // store + per-column partial stats
    float s[4] = {0.f, 0.f, 0.f, 0.f}, s2[4] = {0.f, 0.f, 0.f, 0.f};
#pragma unroll
    for (int r = 0; r < 8; r++) {
        int row = rowBase + ry2 * 8 + r;
        if (row < N_NODES) {
            float4 o = make_float4(ov[r][0], ov[r][1], ov[r][2], ov[r][3]);
            *(float4*)(g_out + row * D + cx2 * 4) = o;
#pragma unroll
            for (int j = 0; j < 4; j++) {
                s[j] += ov[r][j];
                s2[j] += ov[r][j] * ov[r][j];
            }
        }
    }
    __syncthreads();   // smem reuse for reduction
    float* red = sm;   // [8][128] sums, [8][128] sumsq
#pragma unroll
    for (int j = 0; j < 4; j++) {
        red[ry2 * 128 + cx2 * 4 + j] = s[j];
        red[1024 + ry2 * 128 + cx2 * 4 + j] = s2[j];
    }
    __syncthreads();
    if (tid < 128) {
        float ts = 0.f, ts2 = 0.f;
#pragma unroll
        for (int g = 0; g < 8; g++) {
            ts += red[g * 128 + tid];
            ts2 += red[1024 + g * 128 + tid];
        }
        atomicAdd(&g_stats[tid], ts);
        atomicAdd(&g_stats[128 + tid], ts2);
    }
}

// ----------------- BN finalize: fold to per-feature scale/shift -------------
__global__ void k_bn(const float* __restrict__ gamma, const float* __restrict__ beta) {
    int c = threadIdx.x;
    if (c < D) {
        const float invN = 1.0f / (float)N_NODES;
        float mean = g_stats[c] * invN;
        float var = g_stats[D + c] * invN - mean * mean;
        float rstd = rsqrtf(var + 1e-5f);
        float scl = rstd * gamma[c];
        g_aff[c] = scl;
        g_aff[D + c] = beta[c] - mean * scl;
    }
}

// ----------------- final: apply last BN (no relu) to d_out ------------------
__global__ void k_final(float* __restrict__ out) {
    int i = blockIdx.x * blockDim.x + threadIdx.x;   // float4 index
    if (i >= N_NODES * 32) return;
    int c0 = (i & 31) * 4;
    float4 v = ((const float4*)g_out)[i];
    float4 sc = *(const float4*)&g_aff[c0];
    float4 sf = *(const float4*)&g_aff[D + c0];
    v.x = fmaf(v.x, sc.x, sf.x);
    v.y = fmaf(v.y, sc.y, sf.y);
    v.z = fmaf(v.z, sc.z, sf.z);
    v.w = fmaf(v.w, sc.w, sf.w);
    ((float4*)out)[i] = v;
}

// ----------------- launch -----------------
extern "C" void kernel_launch(void* const* d_in, const int* in_sizes, int n_in,
                              void* d_out, int out_size) {
    const int*   x    = (const int*)d_in[0];
    const int*   ei   = (const int*)d_in[1];
    const int*   ea   = (const int*)d_in[2];
    const float* elem = (const float*)d_in[3];
    const float* chir = (const float*)d_in[4];
    const float* bt   = (const float*)d_in[5];
    const float* bd   = (const float*)d_in[6];
    const float* W1   = (const float*)d_in[7];
    const float* b1   = (const float*)d_in[8];
    const float* W2   = (const float*)d_in[9];
    const float* b2   = (const float*)d_in[10];
    const float* bng  = (const float*)d_in[11];
    const float* bnb  = (const float*)d_in[12];
    float* out = (float*)d_out;

    cudaFuncSetAttribute(k_mlp, cudaFuncAttributeMaxDynamicSharedMemorySize, SMEM_MLP);

    k_detect<<<1, 32>>>(x);
    k_embed<<<(N_NODES * 32 + 255) / 256, 256>>>(x, elem, chir);
    k_etab<<<9, 128>>>(bt, bd);
    k_zero_deg<<<(N_NODES + 255) / 256, 256>>>();
    k_hist<<<(N_EDGES + 255) / 256, 256>>>(ei);
    k_scan<<<1, 1024>>>();
    k_fill<<<(N_EDGES + 255) / 256, 256>>>(ei, ea);

    const int mlp_blocks = (N_NODES + 63) / 64;
    for (int l = 0; l < NLAYERS; l++) {
        k_zero_stats<<<1, 256>>>();
        k_agg<<<(N_NODES + 7) / 8, 256>>>(l);
        k_mlp<<<mlp_blocks, 256, SMEM_MLP>>>(W1, b1, W2, b2);
        k_bn<<<1, 128>>>(bng + l * D, bnb + l * D);
    }
    k_final<<<(N_NODES * 32 + 255) / 256, 256>>>(out);
}